// round 9
// baseline (speedup 1.0000x reference)
#include <cuda_runtime.h>
#include <cuda_fp16.h>
#include <cstdint>

#define N_NODES 50000
#define N_EDGES 800000
#define HID 64
#define N_GRAPHS 256
#define BN_EPS 1e-5f

// ---------------- scratch (static device globals; no runtime allocation) ----
__device__ __half g_t[(size_t)N_NODES * HID];   // GEMM input, fp16
__device__ __half g_zh[(size_t)N_NODES * HID];  // layer output, fp16
__device__ __half g_xh[(size_t)N_NODES * HID];  // input features, fp16
__device__ int    g_deg[N_NODES];
__device__ int    g_rowptr[N_NODES + 1];
__device__ int    g_cursor[N_NODES];
__device__ int2   g_csr[N_EDGES];               // {src, weight-bits}
__device__ float  g_stats[3 * 128];             // per layer: [sum(64) | sumsq(64)]
__device__ float  g_pooled[N_GRAPHS * HID];
__device__ int    g_flag[64];                   // domino-scan flags (payload = total+1)

// ---------------- count degrees + convert x to fp16 (fused) -----------------
__global__ void k_count_xh(const int* __restrict__ ei, const float* __restrict__ x) {
    int e = blockIdx.x * 256 + threadIdx.x;
    if (e < N_EDGES) atomicAdd(&g_deg[ei[N_EDGES + e]], 1);
    if (e < (N_NODES * HID) / 16) {
        int base = e * 16;
#pragma unroll
        for (int j = 0; j < 16; j += 2) {
            float2 v = *(const float2*)(x + base + j);
            *(__half2*)(&g_xh[base + j]) = __floats2half2_rn(v.x, v.y);
        }
    }
}

// ---------------- single-kernel domino prefix scan ---------------------------
__global__ void k_scan() {
    __shared__ int sm[1024];
    __shared__ int off_s;
    int t = threadIdx.x, b = blockIdx.x;
    int i = b * 1024 + t;
    int v = (i < N_NODES) ? g_deg[i] : 0;
    if (i < N_NODES) g_deg[i] = 0;            // reset for next call
    sm[t] = v;
    __syncthreads();
    for (int off = 1; off < 1024; off <<= 1) {
        int tmp = (t >= off) ? sm[t - off] : 0;
        __syncthreads();
        sm[t] += tmp;
        __syncthreads();
    }
    if (t == 0) {
        int prev = 0;
        if (b > 0) {
            int f;
            while ((f = atomicAdd(&g_flag[b - 1], 0)) == 0) { }
            prev = f - 1;
            atomicExch(&g_flag[b - 1], 0);    // reset for next call
        }
        if (b < (int)gridDim.x - 1) atomicExch(&g_flag[b], prev + sm[1023] + 1);
        else g_rowptr[N_NODES] = prev + sm[1023];
        off_s = prev;
    }
    __syncthreads();
    if (i < N_NODES) {
        int r = sm[t] - v + off_s;            // exclusive prefix
        g_rowptr[i] = r;
        g_cursor[i] = r;
    }
}

__global__ void k_fill(const int* __restrict__ ei, const float* __restrict__ ew) {
    int e = blockIdx.x * 256 + threadIdx.x;
    if (e < N_EDGES) {
        int dst = ei[N_EDGES + e];
        int p = atomicAdd(&g_cursor[dst], 1);
        g_csr[p] = make_int2(ei[e], __float_as_int(ew[e]));
    }
}

// ---------------- aggregation: 16 lanes/node, fp16 gathers (R7 form) --------
// t[node] = a (.) ( z[node] + sum_e w_e z[src_e] ) + c * (1 + sum_e w_e)
// All 16 lanes load the same CSR entry (HW broadcast); row gather is one
// 128B line per edge. Output stored fp16 into g_t.
__global__ void k_agg(int prev_stats,
                      const float* __restrict__ gam, const float* __restrict__ bet) {
    const __half* __restrict__ zin = (prev_stats < 0) ? (const __half*)g_xh
                                                      : (const __half*)g_zh;
    int l16 = threadIdx.x & 15;
    int node = (blockIdx.x * blockDim.x + threadIdx.x) >> 4;
    if (node >= N_NODES) return;
    int col = l16 * 4;

    float4 a = make_float4(1.f, 1.f, 1.f, 1.f);
    float4 c = make_float4(0.f, 0.f, 0.f, 0.f);
    if (prev_stats >= 0) {
        const float* st = &g_stats[prev_stats * 128];
        const float inv = 1.0f / (float)N_NODES;
        float4 sm = *(const float4*)&st[col];
        float4 sq = *(const float4*)&st[64 + col];
        float4 gv = *(const float4*)&gam[col];
        float4 bv = *(const float4*)&bet[col];
        float mu;
        mu = sm.x * inv; a.x = rsqrtf(sq.x * inv - mu * mu + BN_EPS) * gv.x; c.x = bv.x - mu * a.x;
        mu = sm.y * inv; a.y = rsqrtf(sq.y * inv - mu * mu + BN_EPS) * gv.y; c.y = bv.y - mu * a.y;
        mu = sm.z * inv; a.z = rsqrtf(sq.z * inv - mu * mu + BN_EPS) * gv.z; c.z = bv.z - mu * a.z;
        mu = sm.w * inv; a.w = rsqrtf(sq.w * inv - mu * mu + BN_EPS) * gv.w; c.w = bv.w - mu * a.w;
    }

    int beg = g_rowptr[node], end = g_rowptr[node + 1];
    float sx = 0.f, sy = 0.f, sz = 0.f, sw4 = 0.f, wsum = 0.f;
#pragma unroll 4
    for (int e = beg; e < end; ++e) {
        int2 cw = g_csr[e];
        float w = __int_as_float(cw.y);
        uint2 raw = *(const uint2*)(zin + (size_t)cw.x * HID + col);
        float2 f01 = __half22float2(*(__half2*)&raw.x);
        float2 f23 = __half22float2(*(__half2*)&raw.y);
        sx += w * f01.x; sy += w * f01.y; sz += w * f23.x; sw4 += w * f23.y;
        wsum += w;
    }
    wsum += 1.0f;
    uint2 zraw = *(const uint2*)(zin + (size_t)node * HID + col);
    float2 z01 = __half22float2(*(__half2*)&zraw.x);
    float2 z23 = __half22float2(*(__half2*)&zraw.y);
    union { __half2 h[2]; uint2 u; } pk;
    pk.h[0] = __floats2half2_rn(a.x * (z01.x + sx) + c.x * wsum,
                                a.y * (z01.y + sy) + c.y * wsum);
    pk.h[1] = __floats2half2_rn(a.z * (z23.x + sz) + c.z * wsum,
                                a.w * (z23.y + sw4) + c.w * wsum);
    *(uint2*)(&g_t[(size_t)node * HID + col]) = pk.u;
}

// ---------------- tensor-core GEMM (64x64x64) + bias + relu + stats ---------
// mma.sync.m16n8k16 f16*f16 -> f32. 8 warps: warp w handles m-tile (w&3),
// n-half (w>>2). Stats via shared atomics, then one global atomicAdd per col.
__global__ void k_gemm(const float* __restrict__ W, const float* __restrict__ bias,
                       int layer, int do_relu) {
    __shared__ __half ts_h[64][72];   // t tile, padded stride
    __shared__ __half wt_h[64][72];   // W transposed: wt[n][k]
    __shared__ float  sb[64];
    __shared__ float  sstat[128];
    int tid = threadIdx.x;
    int n0blk = blockIdx.x * 64;

    if (tid < 64) sb[tid] = bias[tid];
    if (tid < 128) sstat[tid] = 0.0f;

    for (int i = tid; i < 4096; i += 256) {   // W[k][n] -> wt_h[n][k], fp16
        int k = i >> 6, n = i & 63;
        wt_h[n][k] = __float2half(W[i]);
    }
    for (int i = tid; i < 512; i += 256) {    // 512 x uint4 = 64x64 halves
        int node = i >> 3, kc = (i & 7) * 8;
        uint4 v = make_uint4(0u, 0u, 0u, 0u);
        if (n0blk + node < N_NODES)
            v = *(const uint4*)(g_t + (size_t)(n0blk + node) * HID + kc);
        *(uint4*)&ts_h[node][kc] = v;
    }
    __syncthreads();

    int warp = tid >> 5, lane = tid & 31;
    int g = lane >> 2, tg = lane & 3;
    int m0 = (warp & 3) * 16;
    int nbase = (warp >> 2) * 32;

    float c0[4], c1[4], c2[4], c3[4];
#pragma unroll
    for (int j = 0; j < 4; ++j) { c0[j]=0.f; c1[j]=0.f; c2[j]=0.f; c3[j]=0.f; }

#pragma unroll
    for (int ks = 0; ks < 4; ++ks) {
        int k0 = ks * 16;
        uint32_t a0 = *(const uint32_t*)&ts_h[m0 + g][k0 + tg * 2];
        uint32_t a1 = *(const uint32_t*)&ts_h[m0 + 8 + g][k0 + tg * 2];
        uint32_t a2 = *(const uint32_t*)&ts_h[m0 + g][k0 + tg * 2 + 8];
        uint32_t a3 = *(const uint32_t*)&ts_h[m0 + 8 + g][k0 + tg * 2 + 8];
#pragma unroll
        for (int j = 0; j < 4; ++j) {
            int nj = nbase + j * 8 + g;
            uint32_t b0 = *(const uint32_t*)&wt_h[nj][k0 + tg * 2];
            uint32_t b1 = *(const uint32_t*)&wt_h[nj][k0 + tg * 2 + 8];
            asm volatile(
                "mma.sync.aligned.m16n8k16.row.col.f32.f16.f16.f32 "
                "{%0,%1,%2,%3}, {%4,%5,%6,%7}, {%8,%9}, {%0,%1,%2,%3};"
                : "+f"(c0[j]), "+f"(c1[j]), "+f"(c2[j]), "+f"(c3[j])
                : "r"(a0), "r"(a1), "r"(a2), "r"(a3), "r"(b0), "r"(b1));
        }
    }

    int node0 = n0blk + m0 + g;
    int node1 = node0 + 8;
#pragma unroll
    for (int j = 0; j < 4; ++j) {
        int col = nbase + j * 8 + tg * 2;
        float bb0 = sb[col], bb1 = sb[col + 1];
        float d00 = c0[j] + bb0, d01 = c1[j] + bb1;
        float d10 = c2[j] + bb0, d11 = c3[j] + bb1;
        if (do_relu) {
            d00 = fmaxf(d00, 0.f); d01 = fmaxf(d01, 0.f);
            d10 = fmaxf(d10, 0.f); d11 = fmaxf(d11, 0.f);
        }
        float s0 = 0.f, s1 = 0.f, q0 = 0.f, q1 = 0.f;
        if (node0 < N_NODES) {
            *(__half2*)&g_zh[(size_t)node0 * HID + col] = __floats2half2_rn(d00, d01);
            s0 += d00; s1 += d01; q0 += d00 * d00; q1 += d01 * d01;
        }
        if (node1 < N_NODES) {
            *(__half2*)&g_zh[(size_t)node1 * HID + col] = __floats2half2_rn(d10, d11);
            s0 += d10; s1 += d11; q0 += d10 * d10; q1 += d11 * d11;
        }
        atomicAdd(&sstat[col], s0);
        atomicAdd(&sstat[col + 1], s1);
        atomicAdd(&sstat[64 + col], q0);
        atomicAdd(&sstat[64 + col + 1], q1);
    }
    __syncthreads();
    if (tid < 128) atomicAdd(&g_stats[layer * 128 + tid], sstat[tid]);
}

// ---------------- layer-3 BN + segmented (sorted-batch) pooling -------------
__global__ void k_norm_pool(const float* __restrict__ gam, const float* __restrict__ bet,
                            const int* __restrict__ batch) {
    int col = threadIdx.x & 63;
    int run = blockIdx.x * (blockDim.x >> 6) + (threadIdx.x >> 6);
    int nruns = gridDim.x * (blockDim.x >> 6);
    int per = (N_NODES + nruns - 1) / nruns;
    int r0 = run * per;
    int r1 = min(N_NODES, r0 + per);

    const float* st = &g_stats[2 * 128];
    const float inv = 1.0f / (float)N_NODES;
    float mu = st[col] * inv;
    float var = st[64 + col] * inv - mu * mu;
    float sc = rsqrtf(var + BN_EPS) * gam[col];
    float bb = bet[col];

    int cur = -1;
    float acc = 0.0f;
    for (int n = r0; n < r1; ++n) {
        int gph = batch[n];
        float v = (__half2float(g_zh[(size_t)n * HID + col]) - mu) * sc + bb;
        if (gph != cur) {
            if (cur >= 0) atomicAdd(&g_pooled[cur * HID + col], acc);
            cur = gph;
            acc = v;
        } else {
            acc += v;
        }
    }
    if (cur >= 0) atomicAdd(&g_pooled[cur * HID + col], acc);
}

// ---------------- final MLP + cleanup of g_pooled / g_stats -----------------
__global__ void k_final(const float* __restrict__ fcW1, const float* __restrict__ fcb1,
                        const float* __restrict__ fcW2, const float* __restrict__ fcb2,
                        float* __restrict__ out) {
    __shared__ float wsm[4096];
    __shared__ float b1s[64];
    __shared__ float w2s[64];
    __shared__ float psm[8][64];
    int tid = threadIdx.x;
    for (int i = tid; i < 4096; i += 256) wsm[i] = fcW1[i];
    if (tid < 64) { b1s[tid] = fcb1[tid]; w2s[tid] = fcW2[tid]; }
    __syncthreads();

    int lane = tid & 31, wid = tid >> 5;
    int gph = blockIdx.x * 8 + wid;
    float p0 = fmaxf(g_pooled[gph * HID + lane], 0.f);
    float p1 = fmaxf(g_pooled[gph * HID + lane + 32], 0.f);
    psm[wid][lane] = p0;
    psm[wid][lane + 32] = p1;
    g_pooled[gph * HID + lane] = 0.0f;
    g_pooled[gph * HID + lane + 32] = 0.0f;
    if (blockIdx.x == 0 && tid < 128) {
        g_stats[tid] = 0.0f; g_stats[128 + tid] = 0.0f; g_stats[256 + tid] = 0.0f;
    }
    __syncwarp();

    float h0 = b1s[lane], h1 = b1s[lane + 32];
#pragma unroll
    for (int k = 0; k < 64; ++k) {
        float pk = psm[wid][k];
        h0 += pk * wsm[k * 64 + lane];
        h1 += pk * wsm[k * 64 + lane + 32];
    }
    float part = fmaxf(h0, 0.f) * w2s[lane] + fmaxf(h1, 0.f) * w2s[lane + 32];
#pragma unroll
    for (int off = 16; off >= 1; off >>= 1)
        part += __shfl_xor_sync(0xffffffffu, part, off);
    if (lane == 0) out[gph] = part + fcb2[0];
}

// ---------------- host launcher ---------------------------------------------
extern "C" void kernel_launch(void* const* d_in, const int* in_sizes, int n_in,
                              void* d_out, int out_size) {
    const float* x     = (const float*)d_in[0];
    const int*   ei    = (const int*)d_in[1];
    const float* ew    = (const float*)d_in[2];
    const int*   batch = (const int*)d_in[3];
    const float *W1 = (const float*)d_in[4],  *b1 = (const float*)d_in[5];
    const float *W2 = (const float*)d_in[6],  *b2 = (const float*)d_in[7];
    const float *W3 = (const float*)d_in[8],  *b3 = (const float*)d_in[9];
    const float *fcW1 = (const float*)d_in[10], *fcb1 = (const float*)d_in[11];
    const float *fcW2 = (const float*)d_in[12], *fcb2 = (const float*)d_in[13];
    const float *g1 = (const float*)d_in[14], *be1 = (const float*)d_in[15];
    const float *g2 = (const float*)d_in[16], *be2 = (const float*)d_in[17];
    const float *g3 = (const float*)d_in[18], *be3 = (const float*)d_in[19];
    float* out = (float*)d_out;

    const int EB = (N_EDGES + 255) / 256;              // 3125
    const int NB1024 = (N_NODES + 1023) / 1024;        // 49
    const int AGG_B = (N_NODES * 16 + 255) / 256;      // 3125
    const int GEMM_B = (N_NODES + 63) / 64;            // 782

    k_count_xh<<<EB, 256>>>(ei, x);                    // our launch 0
    k_scan<<<NB1024, 1024>>>();                        // 1
    k_fill<<<EB, 256>>>(ei, ew);                       // 2

    k_agg<<<AGG_B, 256>>>(-1, nullptr, nullptr);       // 3 (ncu capture slot)
    k_gemm<<<GEMM_B, 256>>>(W1, b1, 0, 1);
    k_agg<<<AGG_B, 256>>>(0, g1, be1);
    k_gemm<<<GEMM_B, 256>>>(W2, b2, 1, 1);
    k_agg<<<AGG_B, 256>>>(1, g2, be2);
    k_gemm<<<GEMM_B, 256>>>(W3, b3, 2, 0);

    k_norm_pool<<<64, 256>>>(g3, be3, batch);
    k_final<<<N_GRAPHS / 8, 256>>>(fcW1, fcb1, fcW2, fcb2, out);
}

// round 10
// speedup vs baseline: 1.0900x; 1.0900x over previous
#include <cuda_runtime.h>
#include <cuda_fp16.h>
#include <cstdint>

#define N_NODES 50000
#define N_EDGES 800000
#define HID 64
#define N_GRAPHS 256
#define BN_EPS 1e-5f

// ---------------- scratch (static device globals; no runtime allocation) ----
__device__ __half g_t[(size_t)N_NODES * HID];   // GEMM input, fp16
__device__ __half g_zh[(size_t)N_NODES * HID];  // layer output, fp16
__device__ __half g_xh[(size_t)N_NODES * HID];  // input features, fp16
__device__ __half g_w16[3 * HID * HID];         // W transposed to [n][k], fp16
__device__ int    g_deg[N_NODES];
__device__ int    g_rowptr[N_NODES + 1];
__device__ int    g_cursor[N_NODES];
__device__ int2   g_csr[N_EDGES];               // {src, weight-bits}
__device__ float  g_stats[3 * 128];             // per layer: [sum(64) | sumsq(64)]
__device__ float  g_pooled[N_GRAPHS * HID];
__device__ int    g_bsums[64];

// ---------------- count degrees + convert x to fp16 (fused) -----------------
__global__ void k_count_xh(const int* __restrict__ ei, const float* __restrict__ x) {
    int e = blockIdx.x * 256 + threadIdx.x;
    if (e < N_EDGES) atomicAdd(&g_deg[ei[N_EDGES + e]], 1);
    if (e < (N_NODES * HID) / 16) {
        int base = e * 16;
#pragma unroll
        for (int j = 0; j < 16; j += 2) {
            float2 v = *(const float2*)(x + base + j);
            *(__half2*)(&g_xh[base + j]) = __floats2half2_rn(v.x, v.y);
        }
    }
}

// ---------------- parallel two-kernel prefix scan (R7 form) -----------------
__global__ void k_scan1() {
    __shared__ int sm[1024];
    int t = threadIdx.x;
    int i = blockIdx.x * 1024 + t;
    int v = (i < N_NODES) ? g_deg[i] : 0;
    if (i < N_NODES) g_deg[i] = 0;            // reset for next call
    sm[t] = v;
    __syncthreads();
    for (int off = 1; off < 1024; off <<= 1) {
        int tmp = (t >= off) ? sm[t - off] : 0;
        __syncthreads();
        sm[t] += tmp;
        __syncthreads();
    }
    if (i < N_NODES) g_rowptr[i] = sm[t] - v;   // exclusive within block
    if (t == 1023) g_bsums[blockIdx.x] = sm[1023];
}

__global__ void k_scan3f() {
    __shared__ int bs[64];
    int t = threadIdx.x;
    int nb = gridDim.x;
    if (t < 64) bs[t] = (t < nb) ? g_bsums[t] : 0;
    __syncthreads();
#pragma unroll
    for (int off = 1; off < 64; off <<= 1) {
        int v = (t < 64 && t >= off) ? bs[t - off] : 0;
        __syncthreads();
        if (t < 64) bs[t] += v;
        __syncthreads();
    }
    int off_s = (blockIdx.x == 0) ? 0 : bs[blockIdx.x - 1];
    if (blockIdx.x == nb - 1 && t == 0) g_rowptr[N_NODES] = bs[nb - 1];
    int i = blockIdx.x * 1024 + t;
    if (i < N_NODES) {
        int v = g_rowptr[i] + off_s;
        g_rowptr[i] = v;
        g_cursor[i] = v;
    }
}

__global__ void k_fill(const int* __restrict__ ei, const float* __restrict__ ew) {
    int e = blockIdx.x * 256 + threadIdx.x;
    if (e < N_EDGES) {
        int dst = ei[N_EDGES + e];
        int p = atomicAdd(&g_cursor[dst], 1);
        g_csr[p] = make_int2(ei[e], __float_as_int(ew[e]));
    }
}

// ---------------- W prep: fp32 [k][n] -> fp16 transposed [n][k] -------------
__global__ void k_wprep(const float* __restrict__ W1, const float* __restrict__ W2,
                        const float* __restrict__ W3) {
    const float* Ws = (blockIdx.y == 0) ? W1 : (blockIdx.y == 1 ? W2 : W3);
    int i = blockIdx.x * 256 + threadIdx.x;
    if (i < HID * HID) {
        int k = i >> 6, n = i & 63;
        g_w16[blockIdx.y * HID * HID + n * HID + k] = __float2half(Ws[i]);
    }
}

// ---------------- aggregation: 16 lanes/node, fp16 gathers ------------------
// t[node] = a (.) ( z[node] + sum_e w_e z[src_e] ) + c * (1 + sum_e w_e)
__global__ void k_agg(int prev_stats,
                      const float* __restrict__ gam, const float* __restrict__ bet) {
    const __half* __restrict__ zin = (prev_stats < 0) ? (const __half*)g_xh
                                                      : (const __half*)g_zh;
    int l16 = threadIdx.x & 15;
    int node = (blockIdx.x * blockDim.x + threadIdx.x) >> 4;
    if (node >= N_NODES) return;
    int col = l16 * 4;

    float4 a = make_float4(1.f, 1.f, 1.f, 1.f);
    float4 c = make_float4(0.f, 0.f, 0.f, 0.f);
    if (prev_stats >= 0) {
        const float* st = &g_stats[prev_stats * 128];
        const float inv = 1.0f / (float)N_NODES;
        float4 sm = *(const float4*)&st[col];
        float4 sq = *(const float4*)&st[64 + col];
        float4 gv = *(const float4*)&gam[col];
        float4 bv = *(const float4*)&bet[col];
        float mu;
        mu = sm.x * inv; a.x = rsqrtf(sq.x * inv - mu * mu + BN_EPS) * gv.x; c.x = bv.x - mu * a.x;
        mu = sm.y * inv; a.y = rsqrtf(sq.y * inv - mu * mu + BN_EPS) * gv.y; c.y = bv.y - mu * a.y;
        mu = sm.z * inv; a.z = rsqrtf(sq.z * inv - mu * mu + BN_EPS) * gv.z; c.z = bv.z - mu * a.z;
        mu = sm.w * inv; a.w = rsqrtf(sq.w * inv - mu * mu + BN_EPS) * gv.w; c.w = bv.w - mu * a.w;
    }

    int beg = g_rowptr[node], end = g_rowptr[node + 1];
    float sx = 0.f, sy = 0.f, sz = 0.f, sw4 = 0.f, wsum = 0.f;
#pragma unroll 4
    for (int e = beg; e < end; ++e) {
        int2 cw = g_csr[e];
        float w = __int_as_float(cw.y);
        uint2 raw = *(const uint2*)(zin + (size_t)cw.x * HID + col);
        float2 f01 = __half22float2(*(__half2*)&raw.x);
        float2 f23 = __half22float2(*(__half2*)&raw.y);
        sx += w * f01.x; sy += w * f01.y; sz += w * f23.x; sw4 += w * f23.y;
        wsum += w;
    }
    wsum += 1.0f;
    uint2 zraw = *(const uint2*)(zin + (size_t)node * HID + col);
    float2 z01 = __half22float2(*(__half2*)&zraw.x);
    float2 z23 = __half22float2(*(__half2*)&zraw.y);
    union { __half2 h[2]; uint2 u; } pk;
    pk.h[0] = __floats2half2_rn(a.x * (z01.x + sx) + c.x * wsum,
                                a.y * (z01.y + sy) + c.y * wsum);
    pk.h[1] = __floats2half2_rn(a.z * (z23.x + sz) + c.z * wsum,
                                a.w * (z23.y + sw4) + c.w * wsum);
    *(uint2*)(&g_t[(size_t)node * HID + col]) = pk.u;
}

// ---------------- tensor-core GEMM (64x64x64) + bias + relu + stats ---------
// Slim setup: both tiles staged with uint4 loads (W pre-converted by k_wprep).
__global__ void k_gemm(const float* __restrict__ bias, int layer, int do_relu) {
    __shared__ __half ts_h[64][72];   // t tile, padded stride
    __shared__ __half wt_h[64][72];   // W [n][k]
    __shared__ float  sb[64];
    __shared__ float  sstat[128];
    int tid = threadIdx.x;
    int n0blk = blockIdx.x * 64;

    if (tid < 64) sb[tid] = bias[tid];
    if (tid < 128) sstat[tid] = 0.0f;

    const __half* wsrc = g_w16 + layer * HID * HID;
#pragma unroll
    for (int i = tid; i < 512; i += 256) {
        int n = i >> 3, kc = (i & 7) * 8;
        *(uint4*)&wt_h[n][kc] = *(const uint4*)&wsrc[n * HID + kc];
    }
#pragma unroll
    for (int i = tid; i < 512; i += 256) {
        int node = i >> 3, kc = (i & 7) * 8;
        uint4 v = make_uint4(0u, 0u, 0u, 0u);
        if (n0blk + node < N_NODES)
            v = *(const uint4*)(g_t + (size_t)(n0blk + node) * HID + kc);
        *(uint4*)&ts_h[node][kc] = v;
    }
    __syncthreads();

    int warp = tid >> 5, lane = tid & 31;
    int g = lane >> 2, tg = lane & 3;
    int m0 = (warp & 3) * 16;
    int nbase = (warp >> 2) * 32;

    float c0[4], c1[4], c2[4], c3[4];
#pragma unroll
    for (int j = 0; j < 4; ++j) { c0[j]=0.f; c1[j]=0.f; c2[j]=0.f; c3[j]=0.f; }

#pragma unroll
    for (int ks = 0; ks < 4; ++ks) {
        int k0 = ks * 16;
        uint32_t a0 = *(const uint32_t*)&ts_h[m0 + g][k0 + tg * 2];
        uint32_t a1 = *(const uint32_t*)&ts_h[m0 + 8 + g][k0 + tg * 2];
        uint32_t a2 = *(const uint32_t*)&ts_h[m0 + g][k0 + tg * 2 + 8];
        uint32_t a3 = *(const uint32_t*)&ts_h[m0 + 8 + g][k0 + tg * 2 + 8];
#pragma unroll
        for (int j = 0; j < 4; ++j) {
            int nj = nbase + j * 8 + g;
            uint32_t b0 = *(const uint32_t*)&wt_h[nj][k0 + tg * 2];
            uint32_t b1 = *(const uint32_t*)&wt_h[nj][k0 + tg * 2 + 8];
            asm volatile(
                "mma.sync.aligned.m16n8k16.row.col.f32.f16.f16.f32 "
                "{%0,%1,%2,%3}, {%4,%5,%6,%7}, {%8,%9}, {%0,%1,%2,%3};"
                : "+f"(c0[j]), "+f"(c1[j]), "+f"(c2[j]), "+f"(c3[j])
                : "r"(a0), "r"(a1), "r"(a2), "r"(a3), "r"(b0), "r"(b1));
        }
    }

    int node0 = n0blk + m0 + g;
    int node1 = node0 + 8;
#pragma unroll
    for (int j = 0; j < 4; ++j) {
        int col = nbase + j * 8 + tg * 2;
        float bb0 = sb[col], bb1 = sb[col + 1];
        float d00 = c0[j] + bb0, d01 = c1[j] + bb1;
        float d10 = c2[j] + bb0, d11 = c3[j] + bb1;
        if (do_relu) {
            d00 = fmaxf(d00, 0.f); d01 = fmaxf(d01, 0.f);
            d10 = fmaxf(d10, 0.f); d11 = fmaxf(d11, 0.f);
        }
        float s0 = 0.f, s1 = 0.f, q0 = 0.f, q1 = 0.f;
        if (node0 < N_NODES) {
            *(__half2*)&g_zh[(size_t)node0 * HID + col] = __floats2half2_rn(d00, d01);
            s0 += d00; s1 += d01; q0 += d00 * d00; q1 += d01 * d01;
        }
        if (node1 < N_NODES) {
            *(__half2*)&g_zh[(size_t)node1 * HID + col] = __floats2half2_rn(d10, d11);
            s0 += d10; s1 += d11; q0 += d10 * d10; q1 += d11 * d11;
        }
        atomicAdd(&sstat[col], s0);
        atomicAdd(&sstat[col + 1], s1);
        atomicAdd(&sstat[64 + col], q0);
        atomicAdd(&sstat[64 + col + 1], q1);
    }
    __syncthreads();
    if (tid < 128) atomicAdd(&g_stats[layer * 128 + tid], sstat[tid]);
}

// ---------------- layer-3 BN + segmented (sorted-batch) pooling -------------
__global__ void k_norm_pool(const float* __restrict__ gam, const float* __restrict__ bet,
                            const int* __restrict__ batch) {
    int col = threadIdx.x & 63;
    int run = blockIdx.x * (blockDim.x >> 6) + (threadIdx.x >> 6);
    int nruns = gridDim.x * (blockDim.x >> 6);
    int per = (N_NODES + nruns - 1) / nruns;
    int r0 = run * per;
    int r1 = min(N_NODES, r0 + per);

    const float* st = &g_stats[2 * 128];
    const float inv = 1.0f / (float)N_NODES;
    float mu = st[col] * inv;
    float var = st[64 + col] * inv - mu * mu;
    float sc = rsqrtf(var + BN_EPS) * gam[col];
    float bb = bet[col];

    int cur = -1;
    float acc = 0.0f;
    for (int n = r0; n < r1; ++n) {
        int gph = batch[n];
        float v = (__half2float(g_zh[(size_t)n * HID + col]) - mu) * sc + bb;
        if (gph != cur) {
            if (cur >= 0) atomicAdd(&g_pooled[cur * HID + col], acc);
            cur = gph;
            acc = v;
        } else {
            acc += v;
        }
    }
    if (cur >= 0) atomicAdd(&g_pooled[cur * HID + col], acc);
}

// ---------------- final MLP + cleanup of g_pooled / g_stats -----------------
__global__ void k_final(const float* __restrict__ fcW1, const float* __restrict__ fcb1,
                        const float* __restrict__ fcW2, const float* __restrict__ fcb2,
                        float* __restrict__ out) {
    __shared__ float wsm[4096];
    __shared__ float b1s[64];
    __shared__ float w2s[64];
    __shared__ float psm[8][64];
    int tid = threadIdx.x;
    for (int i = tid; i < 4096; i += 256) wsm[i] = fcW1[i];
    if (tid < 64) { b1s[tid] = fcb1[tid]; w2s[tid] = fcW2[tid]; }
    __syncthreads();

    int lane = tid & 31, wid = tid >> 5;
    int gph = blockIdx.x * 8 + wid;
    float p0 = fmaxf(g_pooled[gph * HID + lane], 0.f);
    float p1 = fmaxf(g_pooled[gph * HID + lane + 32], 0.f);
    psm[wid][lane] = p0;
    psm[wid][lane + 32] = p1;
    g_pooled[gph * HID + lane] = 0.0f;
    g_pooled[gph * HID + lane + 32] = 0.0f;
    if (blockIdx.x == 0 && tid < 128) {
        g_stats[tid] = 0.0f; g_stats[128 + tid] = 0.0f; g_stats[256 + tid] = 0.0f;
    }
    __syncwarp();

    float h0 = b1s[lane], h1 = b1s[lane + 32];
#pragma unroll
    for (int k = 0; k < 64; ++k) {
        float pk = psm[wid][k];
        h0 += pk * wsm[k * 64 + lane];
        h1 += pk * wsm[k * 64 + lane + 32];
    }
    float part = fmaxf(h0, 0.f) * w2s[lane] + fmaxf(h1, 0.f) * w2s[lane + 32];
#pragma unroll
    for (int off = 16; off >= 1; off >>= 1)
        part += __shfl_xor_sync(0xffffffffu, part, off);
    if (lane == 0) out[gph] = part + fcb2[0];
}

// ---------------- host launcher ---------------------------------------------
extern "C" void kernel_launch(void* const* d_in, const int* in_sizes, int n_in,
                              void* d_out, int out_size) {
    const float* x     = (const float*)d_in[0];
    const int*   ei    = (const int*)d_in[1];
    const float* ew    = (const float*)d_in[2];
    const int*   batch = (const int*)d_in[3];
    const float *W1 = (const float*)d_in[4],  *b1 = (const float*)d_in[5];
    const float *W2 = (const float*)d_in[6],  *b2 = (const float*)d_in[7];
    const float *W3 = (const float*)d_in[8],  *b3 = (const float*)d_in[9];
    const float *fcW1 = (const float*)d_in[10], *fcb1 = (const float*)d_in[11];
    const float *fcW2 = (const float*)d_in[12], *fcb2 = (const float*)d_in[13];
    const float *g1 = (const float*)d_in[14], *be1 = (const float*)d_in[15];
    const float *g2 = (const float*)d_in[16], *be2 = (const float*)d_in[17];
    const float *g3 = (const float*)d_in[18], *be3 = (const float*)d_in[19];
    float* out = (float*)d_out;

    const int EB = (N_EDGES + 255) / 256;              // 3125
    const int NB1024 = (N_NODES + 1023) / 1024;        // 49
    const int AGG_B = (N_NODES * 16 + 255) / 256;      // 3125
    const int GEMM_B = (N_NODES + 63) / 64;            // 782

    k_count_xh<<<EB, 256>>>(ei, x);                    // our launch 0
    k_scan1<<<NB1024, 1024>>>();                       // 1
    k_scan3f<<<NB1024, 1024>>>();                      // 2
    k_fill<<<EB, 256>>>(ei, ew);                       // 3 (ncu capture slot)
    k_wprep<<<dim3(16, 3), 256>>>(W1, W2, W3);         // 4

    k_agg<<<AGG_B, 256>>>(-1, nullptr, nullptr);
    k_gemm<<<GEMM_B, 256>>>(b1, 0, 1);
    k_agg<<<AGG_B, 256>>>(0, g1, be1);
    k_gemm<<<GEMM_B, 256>>>(b2, 1, 1);
    k_agg<<<AGG_B, 256>>>(1, g2, be2);
    k_gemm<<<GEMM_B, 256>>>(b3, 2, 0);

    k_norm_pool<<<64, 256>>>(g3, be3, batch);
    k_final<<<N_GRAPHS / 8, 256>>>(fcW1, fcb1, fcW2, fcb2, out);
}

// round 11
// speedup vs baseline: 1.1812x; 1.0837x over previous
#include <cuda_runtime.h>
#include <cuda_fp16.h>
#include <cstdint>

#define N_NODES 50000
#define N_EDGES 800000
#define HID 64
#define N_GRAPHS 256
#define BN_EPS 1e-5f

// ---------------- scratch (static device globals; no runtime allocation) ----
__device__ __half g_t[(size_t)N_NODES * HID];   // GEMM input, fp16
__device__ __half g_zh[(size_t)N_NODES * HID];  // layer output, fp16
__device__ __half g_xh[(size_t)N_NODES * HID];  // input features, fp16
__device__ int    g_deg[N_NODES];
__device__ int    g_rowptr[N_NODES + 1];
__device__ int    g_cursor[N_NODES];
__device__ int2   g_csr[N_EDGES];               // {src, weight-bits}
__device__ float  g_stats[3 * 128];             // per layer: [sum(64) | sumsq(64)]
__device__ float  g_pooled[N_GRAPHS * HID];
__device__ int    g_bsums[64];

// ---------------- count degrees + convert x to fp16 (fused) -----------------
__global__ void k_count_xh(const int* __restrict__ ei, const float* __restrict__ x) {
    int e = blockIdx.x * 256 + threadIdx.x;
    if (e < N_EDGES) atomicAdd(&g_deg[ei[N_EDGES + e]], 1);
    if (e < (N_NODES * HID) / 16) {
        int base = e * 16;
#pragma unroll
        for (int j = 0; j < 16; j += 2) {
            float2 v = *(const float2*)(x + base + j);
            *(__half2*)(&g_xh[base + j]) = __floats2half2_rn(v.x, v.y);
        }
    }
}

// ---------------- parallel two-kernel prefix scan ----------------------------
__global__ void k_scan1() {
    __shared__ int sm[1024];
    int t = threadIdx.x;
    int i = blockIdx.x * 1024 + t;
    int v = (i < N_NODES) ? g_deg[i] : 0;
    if (i < N_NODES) g_deg[i] = 0;            // reset for next call
    sm[t] = v;
    __syncthreads();
    for (int off = 1; off < 1024; off <<= 1) {
        int tmp = (t >= off) ? sm[t - off] : 0;
        __syncthreads();
        sm[t] += tmp;
        __syncthreads();
    }
    if (i < N_NODES) g_rowptr[i] = sm[t] - v;   // exclusive within block
    if (t == 1023) g_bsums[blockIdx.x] = sm[1023];
}

__global__ void k_scan3f() {
    __shared__ int bs[64];
    int t = threadIdx.x;
    int nb = gridDim.x;
    if (t < 64) bs[t] = (t < nb) ? g_bsums[t] : 0;
    __syncthreads();
#pragma unroll
    for (int off = 1; off < 64; off <<= 1) {
        int v = (t < 64 && t >= off) ? bs[t - off] : 0;
        __syncthreads();
        if (t < 64) bs[t] += v;
        __syncthreads();
    }
    int off_s = (blockIdx.x == 0) ? 0 : bs[blockIdx.x - 1];
    if (blockIdx.x == nb - 1 && t == 0) g_rowptr[N_NODES] = bs[nb - 1];
    int i = blockIdx.x * 1024 + t;
    if (i < N_NODES) {
        int v = g_rowptr[i] + off_s;
        g_rowptr[i] = v;
        g_cursor[i] = v;
    }
}

__global__ void k_fill(const int* __restrict__ ei, const float* __restrict__ ew) {
    int e = blockIdx.x * 256 + threadIdx.x;
    if (e < N_EDGES) {
        int dst = ei[N_EDGES + e];
        int p = atomicAdd(&g_cursor[dst], 1);
        g_csr[p] = make_int2(ei[e], __float_as_int(ew[e]));
    }
}

// ---------------- aggregation: 16 lanes/node, fp16 gathers, unroll 8 --------
// t[node] = a (.) ( z[node] + sum_e w_e z[src_e] ) + c * (1 + sum_e w_e)
__global__ void k_agg(int prev_stats,
                      const float* __restrict__ gam, const float* __restrict__ bet) {
    const __half* __restrict__ zin = (prev_stats < 0) ? (const __half*)g_xh
                                                      : (const __half*)g_zh;
    int l16 = threadIdx.x & 15;
    int node = (blockIdx.x * blockDim.x + threadIdx.x) >> 4;
    if (node >= N_NODES) return;
    int col = l16 * 4;

    float4 a = make_float4(1.f, 1.f, 1.f, 1.f);
    float4 c = make_float4(0.f, 0.f, 0.f, 0.f);
    if (prev_stats >= 0) {
        const float* st = &g_stats[prev_stats * 128];
        const float inv = 1.0f / (float)N_NODES;
        float4 sm = *(const float4*)&st[col];
        float4 sq = *(const float4*)&st[64 + col];
        float4 gv = *(const float4*)&gam[col];
        float4 bv = *(const float4*)&bet[col];
        float mu;
        mu = sm.x * inv; a.x = rsqrtf(sq.x * inv - mu * mu + BN_EPS) * gv.x; c.x = bv.x - mu * a.x;
        mu = sm.y * inv; a.y = rsqrtf(sq.y * inv - mu * mu + BN_EPS) * gv.y; c.y = bv.y - mu * a.y;
        mu = sm.z * inv; a.z = rsqrtf(sq.z * inv - mu * mu + BN_EPS) * gv.z; c.z = bv.z - mu * a.z;
        mu = sm.w * inv; a.w = rsqrtf(sq.w * inv - mu * mu + BN_EPS) * gv.w; c.w = bv.w - mu * a.w;
    }

    int beg = g_rowptr[node], end = g_rowptr[node + 1];
    float sx = 0.f, sy = 0.f, sz = 0.f, sw4 = 0.f, wsum = 0.f;

    // main loop, 8 edges in flight
    int e = beg;
    for (; e + 8 <= end; e += 8) {
        int2  cw[8];
        uint2 raw[8];
#pragma unroll
        for (int j = 0; j < 8; ++j) cw[j] = g_csr[e + j];
#pragma unroll
        for (int j = 0; j < 8; ++j)
            raw[j] = *(const uint2*)(zin + (size_t)cw[j].x * HID + col);
#pragma unroll
        for (int j = 0; j < 8; ++j) {
            float w = __int_as_float(cw[j].y);
            float2 f01 = __half22float2(*(__half2*)&raw[j].x);
            float2 f23 = __half22float2(*(__half2*)&raw[j].y);
            sx += w * f01.x; sy += w * f01.y; sz += w * f23.x; sw4 += w * f23.y;
            wsum += w;
        }
    }
    for (; e < end; ++e) {
        int2 cw = g_csr[e];
        float w = __int_as_float(cw.y);
        uint2 raw = *(const uint2*)(zin + (size_t)cw.x * HID + col);
        float2 f01 = __half22float2(*(__half2*)&raw.x);
        float2 f23 = __half22float2(*(__half2*)&raw.y);
        sx += w * f01.x; sy += w * f01.y; sz += w * f23.x; sw4 += w * f23.y;
        wsum += w;
    }
    wsum += 1.0f;
    uint2 zraw = *(const uint2*)(zin + (size_t)node * HID + col);
    float2 z01 = __half22float2(*(__half2*)&zraw.x);
    float2 z23 = __half22float2(*(__half2*)&zraw.y);
    union { __half2 h[2]; uint2 u; } pk;
    pk.h[0] = __floats2half2_rn(a.x * (z01.x + sx) + c.x * wsum,
                                a.y * (z01.y + sy) + c.y * wsum);
    pk.h[1] = __floats2half2_rn(a.z * (z23.x + sz) + c.z * wsum,
                                a.w * (z23.y + sw4) + c.w * wsum);
    *(uint2*)(&g_t[(size_t)node * HID + col]) = pk.u;
}

// ---------------- fp32 tiled GEMM (64-node tile) + bias + relu + stats ------
// t is fp16 in gmem; converted to fp32 smem tile during staging.
__global__ void k_gemm(const float* __restrict__ W, const float* __restrict__ bias,
                       int layer, int do_relu) {
    __shared__ float ts[64][68];      // [node][k], padded
    __shared__ float ws[64 * 64];     // W[k][col]; reused as stats scratch later
    int tid = threadIdx.x;
    int n0 = blockIdx.x * 64;

    for (int i = tid; i < 4096; i += 256) ws[i] = W[i];
#pragma unroll
    for (int it = 0; it < 4; ++it) {
        int li = it * 256 + tid;          // 1024 quads of 4 halves
        int node = li >> 4, kc = (li & 15) * 4;
        uint2 raw = make_uint2(0u, 0u);
        if (n0 + node < N_NODES)
            raw = *(const uint2*)(g_t + (size_t)(n0 + node) * HID + kc);
        float2 f01 = __half22float2(*(__half2*)&raw.x);
        float2 f23 = __half22float2(*(__half2*)&raw.y);
        *(float4*)&ts[node][kc] = make_float4(f01.x, f01.y, f23.x, f23.y);
    }
    __syncthreads();

    int tx = tid & 15, ty = tid >> 4;
    float acc00=0,acc01=0,acc02=0,acc03=0, acc10=0,acc11=0,acc12=0,acc13=0;
    float acc20=0,acc21=0,acc22=0,acc23=0, acc30=0,acc31=0,acc32=0,acc33=0;
#pragma unroll
    for (int k = 0; k < 64; ++k) {
        float4 wv = *(const float4*)&ws[k * 64 + tx * 4];
        float v0 = ts[ty * 4 + 0][k];
        float v1 = ts[ty * 4 + 1][k];
        float v2 = ts[ty * 4 + 2][k];
        float v3 = ts[ty * 4 + 3][k];
        acc00 += v0*wv.x; acc01 += v0*wv.y; acc02 += v0*wv.z; acc03 += v0*wv.w;
        acc10 += v1*wv.x; acc11 += v1*wv.y; acc12 += v1*wv.z; acc13 += v1*wv.w;
        acc20 += v2*wv.x; acc21 += v2*wv.y; acc22 += v2*wv.z; acc23 += v2*wv.w;
        acc30 += v3*wv.x; acc31 += v3*wv.y; acc32 += v3*wv.z; acc33 += v3*wv.w;
    }

    float4 bv = *(const float4*)&bias[tx * 4];
    float sum0=0,sum1=0,sum2=0,sum3=0, sq0=0,sq1=0,sq2=0,sq3=0;
    float r0[4][4] = {{acc00,acc01,acc02,acc03},{acc10,acc11,acc12,acc13},
                      {acc20,acc21,acc22,acc23},{acc30,acc31,acc32,acc33}};
#pragma unroll
    for (int i = 0; i < 4; ++i) {
        int node = n0 + ty * 4 + i;
        float o0 = r0[i][0] + bv.x, o1 = r0[i][1] + bv.y;
        float o2 = r0[i][2] + bv.z, o3 = r0[i][3] + bv.w;
        if (do_relu) {
            o0 = fmaxf(o0, 0.f); o1 = fmaxf(o1, 0.f);
            o2 = fmaxf(o2, 0.f); o3 = fmaxf(o3, 0.f);
        }
        if (node < N_NODES) {
            union { __half2 h[2]; uint2 u; } pk;
            pk.h[0] = __floats2half2_rn(o0, o1);
            pk.h[1] = __floats2half2_rn(o2, o3);
            *(uint2*)(&g_zh[(size_t)node * HID + tx * 4]) = pk.u;
            sum0 += o0; sum1 += o1; sum2 += o2; sum3 += o3;
            sq0 += o0*o0; sq1 += o1*o1; sq2 += o2*o2; sq3 += o3*o3;
        }
    }

    __syncthreads();
    float* red = ws;
    red[ty * 64 + tx * 4 + 0] = sum0;
    red[ty * 64 + tx * 4 + 1] = sum1;
    red[ty * 64 + tx * 4 + 2] = sum2;
    red[ty * 64 + tx * 4 + 3] = sum3;
    red[1024 + ty * 64 + tx * 4 + 0] = sq0;
    red[1024 + ty * 64 + tx * 4 + 1] = sq1;
    red[1024 + ty * 64 + tx * 4 + 2] = sq2;
    red[1024 + ty * 64 + tx * 4 + 3] = sq3;
    __syncthreads();
    if (tid < 128) {
        int which = tid >> 6, col = tid & 63;
        float S = 0.f;
#pragma unroll
        for (int t2 = 0; t2 < 16; ++t2) S += red[which * 1024 + t2 * 64 + col];
        atomicAdd(&g_stats[layer * 128 + which * 64 + col], S);
    }
}

// ---------------- layer-3 BN + segmented (sorted-batch) pooling -------------
__global__ void k_norm_pool(const float* __restrict__ gam, const float* __restrict__ bet,
                            const int* __restrict__ batch) {
    int col = threadIdx.x & 63;
    int run = blockIdx.x * (blockDim.x >> 6) + (threadIdx.x >> 6);
    int nruns = gridDim.x * (blockDim.x >> 6);
    int per = (N_NODES + nruns - 1) / nruns;
    int r0 = run * per;
    int r1 = min(N_NODES, r0 + per);

    const float* st = &g_stats[2 * 128];
    const float inv = 1.0f / (float)N_NODES;
    float mu = st[col] * inv;
    float var = st[64 + col] * inv - mu * mu;
    float sc = rsqrtf(var + BN_EPS) * gam[col];
    float bb = bet[col];

    int cur = -1;
    float acc = 0.0f;
    for (int n = r0; n < r1; ++n) {
        int gph = batch[n];
        float v = (__half2float(g_zh[(size_t)n * HID + col]) - mu) * sc + bb;
        if (gph != cur) {
            if (cur >= 0) atomicAdd(&g_pooled[cur * HID + col], acc);
            cur = gph;
            acc = v;
        } else {
            acc += v;
        }
    }
    if (cur >= 0) atomicAdd(&g_pooled[cur * HID + col], acc);
}

// ---------------- final MLP + cleanup of g_pooled / g_stats -----------------
__global__ void k_final(const float* __restrict__ fcW1, const float* __restrict__ fcb1,
                        const float* __restrict__ fcW2, const float* __restrict__ fcb2,
                        float* __restrict__ out) {
    __shared__ float wsm[4096];
    __shared__ float b1s[64];
    __shared__ float w2s[64];
    __shared__ float psm[8][64];
    int tid = threadIdx.x;
    for (int i = tid; i < 4096; i += 256) wsm[i] = fcW1[i];
    if (tid < 64) { b1s[tid] = fcb1[tid]; w2s[tid] = fcW2[tid]; }
    __syncthreads();

    int lane = tid & 31, wid = tid >> 5;
    int gph = blockIdx.x * 8 + wid;
    float p0 = fmaxf(g_pooled[gph * HID + lane], 0.f);
    float p1 = fmaxf(g_pooled[gph * HID + lane + 32], 0.f);
    psm[wid][lane] = p0;
    psm[wid][lane + 32] = p1;
    g_pooled[gph * HID + lane] = 0.0f;
    g_pooled[gph * HID + lane + 32] = 0.0f;
    if (blockIdx.x == 0 && tid < 128) {
        g_stats[tid] = 0.0f; g_stats[128 + tid] = 0.0f; g_stats[256 + tid] = 0.0f;
    }
    __syncwarp();

    float h0 = b1s[lane], h1 = b1s[lane + 32];
#pragma unroll
    for (int k = 0; k < 64; ++k) {
        float pk = psm[wid][k];
        h0 += pk * wsm[k * 64 + lane];
        h1 += pk * wsm[k * 64 + lane + 32];
    }
    float part = fmaxf(h0, 0.f) * w2s[lane] + fmaxf(h1, 0.f) * w2s[lane + 32];
#pragma unroll
    for (int off = 16; off >= 1; off >>= 1)
        part += __shfl_xor_sync(0xffffffffu, part, off);
    if (lane == 0) out[gph] = part + fcb2[0];
}

// ---------------- host launcher ---------------------------------------------
extern "C" void kernel_launch(void* const* d_in, const int* in_sizes, int n_in,
                              void* d_out, int out_size) {
    const float* x     = (const float*)d_in[0];
    const int*   ei    = (const int*)d_in[1];
    const float* ew    = (const float*)d_in[2];
    const int*   batch = (const int*)d_in[3];
    const float *W1 = (const float*)d_in[4],  *b1 = (const float*)d_in[5];
    const float *W2 = (const float*)d_in[6],  *b2 = (const float*)d_in[7];
    const float *W3 = (const float*)d_in[8],  *b3 = (const float*)d_in[9];
    const float *fcW1 = (const float*)d_in[10], *fcb1 = (const float*)d_in[11];
    const float *fcW2 = (const float*)d_in[12], *fcb2 = (const float*)d_in[13];
    const float *g1 = (const float*)d_in[14], *be1 = (const float*)d_in[15];
    const float *g2 = (const float*)d_in[16], *be2 = (const float*)d_in[17];
    const float *g3 = (const float*)d_in[18], *be3 = (const float*)d_in[19];
    float* out = (float*)d_out;

    const int EB = (N_EDGES + 255) / 256;              // 3125
    const int NB1024 = (N_NODES + 1023) / 1024;        // 49
    const int AGG_B = (N_NODES * 16 + 255) / 256;      // 3125
    const int GEMM_B = (N_NODES + 63) / 64;            // 782

    k_count_xh<<<EB, 256>>>(ei, x);                    // our launch 0
    k_scan1<<<NB1024, 1024>>>();                       // 1
    k_scan3f<<<NB1024, 1024>>>();                      // 2
    k_fill<<<EB, 256>>>(ei, ew);                       // 3 (ncu capture slot)

    k_agg<<<AGG_B, 256>>>(-1, nullptr, nullptr);
    k_gemm<<<GEMM_B, 256>>>(W1, b1, 0, 1);
    k_agg<<<AGG_B, 256>>>(0, g1, be1);
    k_gemm<<<GEMM_B, 256>>>(W2, b2, 1, 1);
    k_agg<<<AGG_B, 256>>>(1, g2, be2);
    k_gemm<<<GEMM_B, 256>>>(W3, b3, 2, 0);

    k_norm_pool<<<64, 256>>>(g3, be3, batch);
    k_final<<<N_GRAPHS / 8, 256>>>(fcW1, fcb1, fcW2, fcb2, out);
}

// round 12
// speedup vs baseline: 1.2021x; 1.0177x over previous
#include <cuda_runtime.h>
#include <cuda_fp16.h>
#include <cstdint>

#define N_NODES 50000
#define N_EDGES 800000
#define HID 64
#define N_GRAPHS 256
#define BN_EPS 1e-5f

// ---------------- scratch (static device globals; no runtime allocation) ----
__device__ __half g_t[(size_t)N_NODES * HID];   // GEMM input, fp16
__device__ __half g_zh[(size_t)N_NODES * HID];  // layer output, fp16
__device__ __half g_xh[(size_t)N_NODES * HID];  // input features, fp16
__device__ int    g_deg[N_NODES];
__device__ int    g_rowptr[N_NODES + 1];
__device__ int    g_rank[N_EDGES];              // edge rank within its dst
__device__ int2   g_csr[N_EDGES];               // {src, weight-bits}
__device__ float  g_stats[3 * 128];             // per layer: [sum(64) | sumsq(64)]
__device__ float  g_pooled[N_GRAPHS * HID];
__device__ int    g_bsums[64];

// -------- count degrees (rank = atomic return) + convert x to fp16 ----------
__global__ void k_count_xh(const int* __restrict__ ei, const float* __restrict__ x) {
    int e = blockIdx.x * 256 + threadIdx.x;
    if (e < N_EDGES) g_rank[e] = atomicAdd(&g_deg[ei[N_EDGES + e]], 1);
    if (e < (N_NODES * HID) / 16) {
        int base = e * 16;
#pragma unroll
        for (int j = 0; j < 16; j += 2) {
            float2 v = *(const float2*)(x + base + j);
            *(__half2*)(&g_xh[base + j]) = __floats2half2_rn(v.x, v.y);
        }
    }
}

// ---------------- parallel two-kernel prefix scan ----------------------------
__global__ void k_scan1() {
    __shared__ int sm[1024];
    int t = threadIdx.x;
    int i = blockIdx.x * 1024 + t;
    int v = (i < N_NODES) ? g_deg[i] : 0;
    if (i < N_NODES) g_deg[i] = 0;            // reset for next call
    sm[t] = v;
    __syncthreads();
    for (int off = 1; off < 1024; off <<= 1) {
        int tmp = (t >= off) ? sm[t - off] : 0;
        __syncthreads();
        sm[t] += tmp;
        __syncthreads();
    }
    if (i < N_NODES) g_rowptr[i] = sm[t] - v;   // exclusive within block
    if (t == 1023) g_bsums[blockIdx.x] = sm[1023];
}

__global__ void k_scan3f() {
    __shared__ int bs[64];
    int t = threadIdx.x;
    int nb = gridDim.x;
    if (t < 64) bs[t] = (t < nb) ? g_bsums[t] : 0;
    __syncthreads();
#pragma unroll
    for (int off = 1; off < 64; off <<= 1) {
        int v = (t < 64 && t >= off) ? bs[t - off] : 0;
        __syncthreads();
        if (t < 64) bs[t] += v;
        __syncthreads();
    }
    int off_s = (blockIdx.x == 0) ? 0 : bs[blockIdx.x - 1];
    if (blockIdx.x == nb - 1 && t == 0) g_rowptr[N_NODES] = bs[nb - 1];
    int i = blockIdx.x * 1024 + t;
    if (i < N_NODES) g_rowptr[i] += off_s;
}

// ---------------- CSR fill: no atomics (rank precomputed) -------------------
__global__ void k_fill(const int* __restrict__ ei, const float* __restrict__ ew) {
    int e = blockIdx.x * 256 + threadIdx.x;
    if (e < N_EDGES) {
        int dst = ei[N_EDGES + e];
        int p = g_rowptr[dst] + g_rank[e];
        g_csr[p] = make_int2(ei[e], __float_as_int(ew[e]));
    }
}

// ---------------- aggregation: 16 lanes/node, pipelined unroll-8 ------------
// t[node] = a (.) ( z[node] + sum_e w_e z[src_e] ) + c * (1 + sum_e w_e)
__global__ void k_agg(int prev_stats,
                      const float* __restrict__ gam, const float* __restrict__ bet) {
    const __half* __restrict__ zin = (prev_stats < 0) ? (const __half*)g_xh
                                                      : (const __half*)g_zh;
    int l16 = threadIdx.x & 15;
    int node = (blockIdx.x * blockDim.x + threadIdx.x) >> 4;
    if (node >= N_NODES) return;
    int col = l16 * 4;

    float4 a = make_float4(1.f, 1.f, 1.f, 1.f);
    float4 c = make_float4(0.f, 0.f, 0.f, 0.f);
    if (prev_stats >= 0) {
        const float* st = &g_stats[prev_stats * 128];
        const float inv = 1.0f / (float)N_NODES;
        float4 sm = *(const float4*)&st[col];
        float4 sq = *(const float4*)&st[64 + col];
        float4 gv = *(const float4*)&gam[col];
        float4 bv = *(const float4*)&bet[col];
        float mu;
        mu = sm.x * inv; a.x = rsqrtf(sq.x * inv - mu * mu + BN_EPS) * gv.x; c.x = bv.x - mu * a.x;
        mu = sm.y * inv; a.y = rsqrtf(sq.y * inv - mu * mu + BN_EPS) * gv.y; c.y = bv.y - mu * a.y;
        mu = sm.z * inv; a.z = rsqrtf(sq.z * inv - mu * mu + BN_EPS) * gv.z; c.z = bv.z - mu * a.z;
        mu = sm.w * inv; a.w = rsqrtf(sq.w * inv - mu * mu + BN_EPS) * gv.w; c.w = bv.w - mu * a.w;
    }

    int beg = g_rowptr[node], end = g_rowptr[node + 1];
    float sx = 0.f, sy = 0.f, sz = 0.f, sw4 = 0.f, wsum = 0.f;

    int nfull = (end - beg) >> 3;
    int2 cw[8];
    if (nfull > 0) {
#pragma unroll
        for (int j = 0; j < 8; ++j) cw[j] = g_csr[beg + j];
    }
    for (int b = 0; b < nfull; ++b) {
        uint2 raw[8];
#pragma unroll
        for (int j = 0; j < 8; ++j)
            raw[j] = *(const uint2*)(zin + (size_t)cw[j].x * HID + col);
        int2 cwn[8];
        if (b + 1 < nfull) {
            int nb0 = beg + (b + 1) * 8;
#pragma unroll
            for (int j = 0; j < 8; ++j) cwn[j] = g_csr[nb0 + j];
        }
#pragma unroll
        for (int j = 0; j < 8; ++j) {
            float w = __int_as_float(cw[j].y);
            float2 f01 = __half22float2(*(__half2*)&raw[j].x);
            float2 f23 = __half22float2(*(__half2*)&raw[j].y);
            sx += w * f01.x; sy += w * f01.y; sz += w * f23.x; sw4 += w * f23.y;
            wsum += w;
        }
#pragma unroll
        for (int j = 0; j < 8; ++j) cw[j] = cwn[j];
    }
    for (int e = beg + nfull * 8; e < end; ++e) {
        int2 cwr = g_csr[e];
        float w = __int_as_float(cwr.y);
        uint2 raw = *(const uint2*)(zin + (size_t)cwr.x * HID + col);
        float2 f01 = __half22float2(*(__half2*)&raw.x);
        float2 f23 = __half22float2(*(__half2*)&raw.y);
        sx += w * f01.x; sy += w * f01.y; sz += w * f23.x; sw4 += w * f23.y;
        wsum += w;
    }
    wsum += 1.0f;
    uint2 zraw = *(const uint2*)(zin + (size_t)node * HID + col);
    float2 z01 = __half22float2(*(__half2*)&zraw.x);
    float2 z23 = __half22float2(*(__half2*)&zraw.y);
    union { __half2 h[2]; uint2 u; } pk;
    pk.h[0] = __floats2half2_rn(a.x * (z01.x + sx) + c.x * wsum,
                                a.y * (z01.y + sy) + c.y * wsum);
    pk.h[1] = __floats2half2_rn(a.z * (z23.x + sz) + c.z * wsum,
                                a.w * (z23.y + sw4) + c.w * wsum);
    *(uint2*)(&g_t[(size_t)node * HID + col]) = pk.u;
}

// ---------------- fp32 tiled GEMM (64-node tile) + bias + relu + stats ------
__global__ void k_gemm(const float* __restrict__ W, const float* __restrict__ bias,
                       int layer, int do_relu) {
    __shared__ float ts[64][68];      // [node][k], padded
    __shared__ float ws[64 * 64];     // W[k][col]; reused as stats scratch later
    int tid = threadIdx.x;
    int n0 = blockIdx.x * 64;

    for (int i = tid; i < 4096; i += 256) ws[i] = W[i];
#pragma unroll
    for (int it = 0; it < 4; ++it) {
        int li = it * 256 + tid;
        int node = li >> 4, kc = (li & 15) * 4;
        uint2 raw = make_uint2(0u, 0u);
        if (n0 + node < N_NODES)
            raw = *(const uint2*)(g_t + (size_t)(n0 + node) * HID + kc);
        float2 f01 = __half22float2(*(__half2*)&raw.x);
        float2 f23 = __half22float2(*(__half2*)&raw.y);
        *(float4*)&ts[node][kc] = make_float4(f01.x, f01.y, f23.x, f23.y);
    }
    __syncthreads();

    int tx = tid & 15, ty = tid >> 4;
    float acc00=0,acc01=0,acc02=0,acc03=0, acc10=0,acc11=0,acc12=0,acc13=0;
    float acc20=0,acc21=0,acc22=0,acc23=0, acc30=0,acc31=0,acc32=0,acc33=0;
#pragma unroll
    for (int k = 0; k < 64; ++k) {
        float4 wv = *(const float4*)&ws[k * 64 + tx * 4];
        float v0 = ts[ty * 4 + 0][k];
        float v1 = ts[ty * 4 + 1][k];
        float v2 = ts[ty * 4 + 2][k];
        float v3 = ts[ty * 4 + 3][k];
        acc00 += v0*wv.x; acc01 += v0*wv.y; acc02 += v0*wv.z; acc03 += v0*wv.w;
        acc10 += v1*wv.x; acc11 += v1*wv.y; acc12 += v1*wv.z; acc13 += v1*wv.w;
        acc20 += v2*wv.x; acc21 += v2*wv.y; acc22 += v2*wv.z; acc23 += v2*wv.w;
        acc30 += v3*wv.x; acc31 += v3*wv.y; acc32 += v3*wv.z; acc33 += v3*wv.w;
    }

    float4 bv = *(const float4*)&bias[tx * 4];
    float sum0=0,sum1=0,sum2=0,sum3=0, sq0=0,sq1=0,sq2=0,sq3=0;
    float r0[4][4] = {{acc00,acc01,acc02,acc03},{acc10,acc11,acc12,acc13},
                      {acc20,acc21,acc22,acc23},{acc30,acc31,acc32,acc33}};
#pragma unroll
    for (int i = 0; i < 4; ++i) {
        int node = n0 + ty * 4 + i;
        float o0 = r0[i][0] + bv.x, o1 = r0[i][1] + bv.y;
        float o2 = r0[i][2] + bv.z, o3 = r0[i][3] + bv.w;
        if (do_relu) {
            o0 = fmaxf(o0, 0.f); o1 = fmaxf(o1, 0.f);
            o2 = fmaxf(o2, 0.f); o3 = fmaxf(o3, 0.f);
        }
        if (node < N_NODES) {
            union { __half2 h[2]; uint2 u; } pk;
            pk.h[0] = __floats2half2_rn(o0, o1);
            pk.h[1] = __floats2half2_rn(o2, o3);
            *(uint2*)(&g_zh[(size_t)node * HID + tx * 4]) = pk.u;
            sum0 += o0; sum1 += o1; sum2 += o2; sum3 += o3;
            sq0 += o0*o0; sq1 += o1*o1; sq2 += o2*o2; sq3 += o3*o3;
        }
    }

    __syncthreads();
    float* red = ws;
    red[ty * 64 + tx * 4 + 0] = sum0;
    red[ty * 64 + tx * 4 + 1] = sum1;
    red[ty * 64 + tx * 4 + 2] = sum2;
    red[ty * 64 + tx * 4 + 3] = sum3;
    red[1024 + ty * 64 + tx * 4 + 0] = sq0;
    red[1024 + ty * 64 + tx * 4 + 1] = sq1;
    red[1024 + ty * 64 + tx * 4 + 2] = sq2;
    red[1024 + ty * 64 + tx * 4 + 3] = sq3;
    __syncthreads();
    if (tid < 128) {
        int which = tid >> 6, col = tid & 63;
        float S = 0.f;
#pragma unroll
        for (int t2 = 0; t2 < 16; ++t2) S += red[which * 1024 + t2 * 64 + col];
        atomicAdd(&g_stats[layer * 128 + which * 64 + col], S);
    }
}

// ---------------- layer-3 BN + segmented (sorted-batch) pooling -------------
__global__ void k_norm_pool(const float* __restrict__ gam, const float* __restrict__ bet,
                            const int* __restrict__ batch) {
    int col = threadIdx.x & 63;
    int run = blockIdx.x * (blockDim.x >> 6) + (threadIdx.x >> 6);
    int nruns = gridDim.x * (blockDim.x >> 6);
    int per = (N_NODES + nruns - 1) / nruns;
    int r0 = run * per;
    int r1 = min(N_NODES, r0 + per);

    const float* st = &g_stats[2 * 128];
    const float inv = 1.0f / (float)N_NODES;
    float mu = st[col] * inv;
    float var = st[64 + col] * inv - mu * mu;
    float sc = rsqrtf(var + BN_EPS) * gam[col];
    float bb = bet[col];

    int cur = -1;
    float acc = 0.0f;
    for (int n = r0; n < r1; ++n) {
        int gph = batch[n];
        float v = (__half2float(g_zh[(size_t)n * HID + col]) - mu) * sc + bb;
        if (gph != cur) {
            if (cur >= 0) atomicAdd(&g_pooled[cur * HID + col], acc);
            cur = gph;
            acc = v;
        } else {
            acc += v;
        }
    }
    if (cur >= 0) atomicAdd(&g_pooled[cur * HID + col], acc);
}

// ---------------- final MLP + cleanup of g_pooled / g_stats -----------------
__global__ void k_final(const float* __restrict__ fcW1, const float* __restrict__ fcb1,
                        const float* __restrict__ fcW2, const float* __restrict__ fcb2,
                        float* __restrict__ out) {
    __shared__ float wsm[4096];
    __shared__ float b1s[64];
    __shared__ float w2s[64];
    __shared__ float psm[8][64];
    int tid = threadIdx.x;
    for (int i = tid; i < 4096; i += 256) wsm[i] = fcW1[i];
    if (tid < 64) { b1s[tid] = fcb1[tid]; w2s[tid] = fcW2[tid]; }
    __syncthreads();

    int lane = tid & 31, wid = tid >> 5;
    int gph = blockIdx.x * 8 + wid;
    float p0 = fmaxf(g_pooled[gph * HID + lane], 0.f);
    float p1 = fmaxf(g_pooled[gph * HID + lane + 32], 0.f);
    psm[wid][lane] = p0;
    psm[wid][lane + 32] = p1;
    g_pooled[gph * HID + lane] = 0.0f;
    g_pooled[gph * HID + lane + 32] = 0.0f;
    if (blockIdx.x == 0 && tid < 128) {
        g_stats[tid] = 0.0f; g_stats[128 + tid] = 0.0f; g_stats[256 + tid] = 0.0f;
    }
    __syncwarp();

    float h0 = b1s[lane], h1 = b1s[lane + 32];
#pragma unroll
    for (int k = 0; k < 64; ++k) {
        float pk = psm[wid][k];
        h0 += pk * wsm[k * 64 + lane];
        h1 += pk * wsm[k * 64 + lane + 32];
    }
    float part = fmaxf(h0, 0.f) * w2s[lane] + fmaxf(h1, 0.f) * w2s[lane + 32];
#pragma unroll
    for (int off = 16; off >= 1; off >>= 1)
        part += __shfl_xor_sync(0xffffffffu, part, off);
    if (lane == 0) out[gph] = part + fcb2[0];
}

// ---------------- host launcher ---------------------------------------------
extern "C" void kernel_launch(void* const* d_in, const int* in_sizes, int n_in,
                              void* d_out, int out_size) {
    const float* x     = (const float*)d_in[0];
    const int*   ei    = (const int*)d_in[1];
    const float* ew    = (const float*)d_in[2];
    const int*   batch = (const int*)d_in[3];
    const float *W1 = (const float*)d_in[4],  *b1 = (const float*)d_in[5];
    const float *W2 = (const float*)d_in[6],  *b2 = (const float*)d_in[7];
    const float *W3 = (const float*)d_in[8],  *b3 = (const float*)d_in[9];
    const float *fcW1 = (const float*)d_in[10], *fcb1 = (const float*)d_in[11];
    const float *fcW2 = (const float*)d_in[12], *fcb2 = (const float*)d_in[13];
    const float *g1 = (const float*)d_in[14], *be1 = (const float*)d_in[15];
    const float *g2 = (const float*)d_in[16], *be2 = (const float*)d_in[17];
    const float *g3 = (const float*)d_in[18], *be3 = (const float*)d_in[19];
    float* out = (float*)d_out;

    const int EB = (N_EDGES + 255) / 256;              // 3125
    const int NB1024 = (N_NODES + 1023) / 1024;        // 49
    const int AGG_B = (N_NODES * 16 + 255) / 256;      // 3125
    const int GEMM_B = (N_NODES + 63) / 64;            // 782

    k_count_xh<<<EB, 256>>>(ei, x);                    // our launch 0
    k_scan1<<<NB1024, 1024>>>();                       // 1
    k_scan3f<<<NB1024, 1024>>>();                      // 2
    k_fill<<<EB, 256>>>(ei, ew);                       // 3 (ncu capture slot)

    k_agg<<<AGG_B, 256>>>(-1, nullptr, nullptr);
    k_gemm<<<GEMM_B, 256>>>(W1, b1, 0, 1);
    k_agg<<<AGG_B, 256>>>(0, g1, be1);
    k_gemm<<<GEMM_B, 256>>>(W2, b2, 1, 1);
    k_agg<<<AGG_B, 256>>>(1, g2, be2);
    k_gemm<<<GEMM_B, 256>>>(W3, b3, 2, 0);

    k_norm_pool<<<64, 256>>>(g3, be3, batch);
    k_final<<<N_GRAPHS / 8, 256>>>(fcW1, fcb1, fcW2, fcb2, out);
}

// round 13
// speedup vs baseline: 1.2846x; 1.0686x over previous
#include <cuda_runtime.h>
#include <cuda_fp16.h>
#include <cstdint>

#define N_NODES 50000
#define N_EDGES 800000
#define HID 64
#define N_GRAPHS 256
#define BN_EPS 1e-5f

// ---------------- scratch (static device globals; no runtime allocation) ----
__device__ __half g_t[(size_t)N_NODES * HID];   // GEMM input, fp16
__device__ __half g_zh[(size_t)N_NODES * HID];  // layer output, fp16
__device__ __half g_xh[(size_t)N_NODES * HID];  // input features, fp16
__device__ int    g_deg[N_NODES];
__device__ int    g_rowptr[N_NODES + 1];        // block-local exclusive prefix
__device__ int    g_bsoff[64];                  // per-1024-block global offsets
__device__ int    g_rank[N_EDGES];              // edge rank within its dst
__device__ int2   g_csr[N_EDGES];               // {src, weight-bits}
__device__ float  g_stats[3 * 128];             // per layer: [sum(64) | sumsq(64)]
__device__ float  g_pooled[N_GRAPHS * HID];
__device__ int    g_bsums[64];
__device__ int    g_done;                       // scan completion counter

// -------- count degrees (rank = atomic return) + convert x to fp16 ----------
__global__ void k_count_xh(const int* __restrict__ ei, const float* __restrict__ x) {
    int e = blockIdx.x * 256 + threadIdx.x;
    if (e < N_EDGES) g_rank[e] = atomicAdd(&g_deg[ei[N_EDGES + e]], 1);
    if (e < (N_NODES * HID) / 16) {
        int base = e * 16;
#pragma unroll
        for (int j = 0; j < 16; j += 2) {
            float2 v = *(const float2*)(x + base + j);
            *(__half2*)(&g_xh[base + j]) = __floats2half2_rn(v.x, v.y);
        }
    }
}

// ---------------- single-kernel prefix scan ----------------------------------
// Each block: local scan -> g_rowptr (block-local exclusive), total -> g_bsums.
// Last-finishing block (atomic counter) scans the 49 block totals -> g_bsoff.
// Consumers add g_bsoff[i >> 10] on the fly.
__global__ void k_scan() {
    __shared__ int sm[1024];
    __shared__ int lastflag;
    int t = threadIdx.x, b = blockIdx.x;
    int i = b * 1024 + t;
    int v = (i < N_NODES) ? g_deg[i] : 0;
    if (i < N_NODES) g_deg[i] = 0;            // reset for next call
    sm[t] = v;
    __syncthreads();
    for (int off = 1; off < 1024; off <<= 1) {
        int tmp = (t >= off) ? sm[t - off] : 0;
        __syncthreads();
        sm[t] += tmp;
        __syncthreads();
    }
    if (i <= N_NODES) g_rowptr[i] = sm[t] - v;   // block-local exclusive
    if (t == 1023) g_bsums[b] = sm[1023];

    __threadfence();
    if (t == 0) lastflag = (atomicAdd(&g_done, 1) == (int)gridDim.x - 1);
    __syncthreads();
    if (lastflag) {
        __threadfence();                       // acquire all blocks' bsums
        int val = (t < (int)gridDim.x) ? g_bsums[t] : 0;
        sm[t] = val;
        __syncthreads();
        for (int off = 1; off < 64; off <<= 1) {
            int tmp = (t >= off) ? sm[t - off] : 0;
            __syncthreads();
            sm[t] += tmp;
            __syncthreads();
        }
        if (t < 64) g_bsoff[t] = (t < (int)gridDim.x) ? (sm[t] - val) : 0;
        if (t == 0) g_done = 0;                // reset for next call
    }
}

// ---------------- CSR fill: no atomics (rank precomputed) -------------------
__global__ void k_fill(const int* __restrict__ ei, const float* __restrict__ ew) {
    int e = blockIdx.x * 256 + threadIdx.x;
    if (e < N_EDGES) {
        int dst = ei[N_EDGES + e];
        int p = g_rowptr[dst] + g_bsoff[dst >> 10] + g_rank[e];
        g_csr[p] = make_int2(ei[e], __float_as_int(ew[e]));
    }
}

// ---------------- aggregation: 16 lanes/node, masked batches of 8 -----------
// t[node] = a (.) ( z[node] + sum_e w_e z[src_e] ) + c * (1 + sum_e w_e)
// Last batch padded with (src=node, w=0): exact, keeps 8 gathers in flight.
__global__ void k_agg(int prev_stats,
                      const float* __restrict__ gam, const float* __restrict__ bet) {
    const __half* __restrict__ zin = (prev_stats < 0) ? (const __half*)g_xh
                                                      : (const __half*)g_zh;
    int l16 = threadIdx.x & 15;
    int node = (blockIdx.x * blockDim.x + threadIdx.x) >> 4;
    if (node >= N_NODES) return;
    int col = l16 * 4;

    float4 a = make_float4(1.f, 1.f, 1.f, 1.f);
    float4 c = make_float4(0.f, 0.f, 0.f, 0.f);
    if (prev_stats >= 0) {
        const float* st = &g_stats[prev_stats * 128];
        const float inv = 1.0f / (float)N_NODES;
        float4 sm = *(const float4*)&st[col];
        float4 sq = *(const float4*)&st[64 + col];
        float4 gv = *(const float4*)&gam[col];
        float4 bv = *(const float4*)&bet[col];
        float mu;
        mu = sm.x * inv; a.x = rsqrtf(sq.x * inv - mu * mu + BN_EPS) * gv.x; c.x = bv.x - mu * a.x;
        mu = sm.y * inv; a.y = rsqrtf(sq.y * inv - mu * mu + BN_EPS) * gv.y; c.y = bv.y - mu * a.y;
        mu = sm.z * inv; a.z = rsqrtf(sq.z * inv - mu * mu + BN_EPS) * gv.z; c.z = bv.z - mu * a.z;
        mu = sm.w * inv; a.w = rsqrtf(sq.w * inv - mu * mu + BN_EPS) * gv.w; c.w = bv.w - mu * a.w;
    }

    int beg = g_rowptr[node] + g_bsoff[node >> 10];
    int end = g_rowptr[node + 1] + g_bsoff[(node + 1) >> 10];
    float sx = 0.f, sy = 0.f, sz = 0.f, sw4 = 0.f, wsum = 0.f;

    int nb = (end - beg + 7) >> 3;             // masked batches of 8
    int2 cw[8];
    if (nb > 0) {
#pragma unroll
        for (int j = 0; j < 8; ++j) {
            int idx = beg + j;
            cw[j] = (idx < end) ? g_csr[idx] : make_int2(node, 0);
        }
    }
    for (int b2 = 0; b2 < nb; ++b2) {
        uint2 raw[8];
#pragma unroll
        for (int j = 0; j < 8; ++j)
            raw[j] = *(const uint2*)(zin + (size_t)cw[j].x * HID + col);
        int2 cwn[8];
        if (b2 + 1 < nb) {
            int nb0 = beg + (b2 + 1) * 8;
#pragma unroll
            for (int j = 0; j < 8; ++j) {
                int idx = nb0 + j;
                cwn[j] = (idx < end) ? g_csr[idx] : make_int2(node, 0);
            }
        }
#pragma unroll
        for (int j = 0; j < 8; ++j) {
            float w = __int_as_float(cw[j].y);
            float2 f01 = __half22float2(*(__half2*)&raw[j].x);
            float2 f23 = __half22float2(*(__half2*)&raw[j].y);
            sx += w * f01.x; sy += w * f01.y; sz += w * f23.x; sw4 += w * f23.y;
            wsum += w;
        }
#pragma unroll
        for (int j = 0; j < 8; ++j) cw[j] = cwn[j];
    }
    wsum += 1.0f;
    uint2 zraw = *(const uint2*)(zin + (size_t)node * HID + col);
    float2 z01 = __half22float2(*(__half2*)&zraw.x);
    float2 z23 = __half22float2(*(__half2*)&zraw.y);
    union { __half2 h[2]; uint2 u; } pk;
    pk.h[0] = __floats2half2_rn(a.x * (z01.x + sx) + c.x * wsum,
                                a.y * (z01.y + sy) + c.y * wsum);
    pk.h[1] = __floats2half2_rn(a.z * (z23.x + sz) + c.z * wsum,
                                a.w * (z23.y + sw4) + c.w * wsum);
    *(uint2*)(&g_t[(size_t)node * HID + col]) = pk.u;
}

// ---------------- fp32 tiled GEMM (64-node tile) + bias + relu + stats ------
__global__ void k_gemm(const float* __restrict__ W, const float* __restrict__ bias,
                       int layer, int do_relu) {
    __shared__ float ts[64][68];      // [node][k], padded
    __shared__ float ws[64 * 64];     // W[k][col]; reused as stats scratch later
    int tid = threadIdx.x;
    int n0 = blockIdx.x * 64;

    for (int i = tid; i < 4096; i += 256) ws[i] = W[i];
#pragma unroll
    for (int it = 0; it < 4; ++it) {
        int li = it * 256 + tid;
        int node = li >> 4, kc = (li & 15) * 4;
        uint2 raw = make_uint2(0u, 0u);
        if (n0 + node < N_NODES)
            raw = *(const uint2*)(g_t + (size_t)(n0 + node) * HID + kc);
        float2 f01 = __half22float2(*(__half2*)&raw.x);
        float2 f23 = __half22float2(*(__half2*)&raw.y);
        *(float4*)&ts[node][kc] = make_float4(f01.x, f01.y, f23.x, f23.y);
    }
    __syncthreads();

    int tx = tid & 15, ty = tid >> 4;
    float acc00=0,acc01=0,acc02=0,acc03=0, acc10=0,acc11=0,acc12=0,acc13=0;
    float acc20=0,acc21=0,acc22=0,acc23=0, acc30=0,acc31=0,acc32=0,acc33=0;
#pragma unroll
    for (int k = 0; k < 64; ++k) {
        float4 wv = *(const float4*)&ws[k * 64 + tx * 4];
        float v0 = ts[ty * 4 + 0][k];
        float v1 = ts[ty * 4 + 1][k];
        float v2 = ts[ty * 4 + 2][k];
        float v3 = ts[ty * 4 + 3][k];
        acc00 += v0*wv.x; acc01 += v0*wv.y; acc02 += v0*wv.z; acc03 += v0*wv.w;
        acc10 += v1*wv.x; acc11 += v1*wv.y; acc12 += v1*wv.z; acc13 += v1*wv.w;
        acc20 += v2*wv.x; acc21 += v2*wv.y; acc22 += v2*wv.z; acc23 += v2*wv.w;
        acc30 += v3*wv.x; acc31 += v3*wv.y; acc32 += v3*wv.z; acc33 += v3*wv.w;
    }

    float4 bv = *(const float4*)&bias[tx * 4];
    float sum0=0,sum1=0,sum2=0,sum3=0, sq0=0,sq1=0,sq2=0,sq3=0;
    float r0[4][4] = {{acc00,acc01,acc02,acc03},{acc10,acc11,acc12,acc13},
                      {acc20,acc21,acc22,acc23},{acc30,acc31,acc32,acc33}};
#pragma unroll
    for (int i = 0; i < 4; ++i) {
        int node = n0 + ty * 4 + i;
        float o0 = r0[i][0] + bv.x, o1 = r0[i][1] + bv.y;
        float o2 = r0[i][2] + bv.z, o3 = r0[i][3] + bv.w;
        if (do_relu) {
            o0 = fmaxf(o0, 0.f); o1 = fmaxf(o1, 0.f);
            o2 = fmaxf(o2, 0.f); o3 = fmaxf(o3, 0.f);
        }
        if (node < N_NODES) {
            union { __half2 h[2]; uint2 u; } pk;
            pk.h[0] = __floats2half2_rn(o0, o1);
            pk.h[1] = __floats2half2_rn(o2, o3);
            *(uint2*)(&g_zh[(size_t)node * HID + tx * 4]) = pk.u;
            sum0 += o0; sum1 += o1; sum2 += o2; sum3 += o3;
            sq0 += o0*o0; sq1 += o1*o1; sq2 += o2*o2; sq3 += o3*o3;
        }
    }

    __syncthreads();
    float* red = ws;
    red[ty * 64 + tx * 4 + 0] = sum0;
    red[ty * 64 + tx * 4 + 1] = sum1;
    red[ty * 64 + tx * 4 + 2] = sum2;
    red[ty * 64 + tx * 4 + 3] = sum3;
    red[1024 + ty * 64 + tx * 4 + 0] = sq0;
    red[1024 + ty * 64 + tx * 4 + 1] = sq1;
    red[1024 + ty * 64 + tx * 4 + 2] = sq2;
    red[1024 + ty * 64 + tx * 4 + 3] = sq3;
    __syncthreads();
    if (tid < 128) {
        int which = tid >> 6, col = tid & 63;
        float S = 0.f;
#pragma unroll
        for (int t2 = 0; t2 < 16; ++t2) S += red[which * 1024 + t2 * 64 + col];
        atomicAdd(&g_stats[layer * 128 + which * 64 + col], S);
    }
}

// ---------------- layer-3 BN + segmented (sorted-batch) pooling -------------
__global__ void k_norm_pool(const float* __restrict__ gam, const float* __restrict__ bet,
                            const int* __restrict__ batch) {
    int col = threadIdx.x & 63;
    int run = blockIdx.x * (blockDim.x >> 6) + (threadIdx.x >> 6);
    int nruns = gridDim.x * (blockDim.x >> 6);
    int per = (N_NODES + nruns - 1) / nruns;
    int r0 = run * per;
    int r1 = min(N_NODES, r0 + per);

    const float* st = &g_stats[2 * 128];
    const float inv = 1.0f / (float)N_NODES;
    float mu = st[col] * inv;
    float var = st[64 + col] * inv - mu * mu;
    float sc = rsqrtf(var + BN_EPS) * gam[col];
    float bb = bet[col];

    int cur = -1;
    float acc = 0.0f;
    for (int n = r0; n < r1; ++n) {
        int gph = batch[n];
        float v = (__half2float(g_zh[(size_t)n * HID + col]) - mu) * sc + bb;
        if (gph != cur) {
            if (cur >= 0) atomicAdd(&g_pooled[cur * HID + col], acc);
            cur = gph;
            acc = v;
        } else {
            acc += v;
        }
    }
    if (cur >= 0) atomicAdd(&g_pooled[cur * HID + col], acc);
}

// ---------------- final MLP + cleanup of g_pooled / g_stats -----------------
__global__ void k_final(const float* __restrict__ fcW1, const float* __restrict__ fcb1,
                        const float* __restrict__ fcW2, const float* __restrict__ fcb2,
                        float* __restrict__ out) {
    __shared__ float wsm[4096];
    __shared__ float b1s[64];
    __shared__ float w2s[64];
    __shared__ float psm[8][64];
    int tid = threadIdx.x;
    for (int i = tid; i < 4096; i += 256) wsm[i] = fcW1[i];
    if (tid < 64) { b1s[tid] = fcb1[tid]; w2s[tid] = fcW2[tid]; }
    __syncthreads();

    int lane = tid & 31, wid = tid >> 5;
    int gph = blockIdx.x * 8 + wid;
    float p0 = fmaxf(g_pooled[gph * HID + lane], 0.f);
    float p1 = fmaxf(g_pooled[gph * HID + lane + 32], 0.f);
    psm[wid][lane] = p0;
    psm[wid][lane + 32] = p1;
    g_pooled[gph * HID + lane] = 0.0f;
    g_pooled[gph * HID + lane + 32] = 0.0f;
    if (blockIdx.x == 0 && tid < 128) {
        g_stats[tid] = 0.0f; g_stats[128 + tid] = 0.0f; g_stats[256 + tid] = 0.0f;
    }
    __syncwarp();

    float h0 = b1s[lane], h1 = b1s[lane + 32];
#pragma unroll
    for (int k = 0; k < 64; ++k) {
        float pk = psm[wid][k];
        h0 += pk * wsm[k * 64 + lane];
        h1 += pk * wsm[k * 64 + lane + 32];
    }
    float part = fmaxf(h0, 0.f) * w2s[lane] + fmaxf(h1, 0.f) * w2s[lane + 32];
#pragma unroll
    for (int off = 16; off >= 1; off >>= 1)
        part += __shfl_xor_sync(0xffffffffu, part, off);
    if (lane == 0) out[gph] = part + fcb2[0];
}

// ---------------- host launcher ---------------------------------------------
extern "C" void kernel_launch(void* const* d_in, const int* in_sizes, int n_in,
                              void* d_out, int out_size) {
    const float* x     = (const float*)d_in[0];
    const int*   ei    = (const int*)d_in[1];
    const float* ew    = (const float*)d_in[2];
    const int*   batch = (const int*)d_in[3];
    const float *W1 = (const float*)d_in[4],  *b1 = (const float*)d_in[5];
    const float *W2 = (const float*)d_in[6],  *b2 = (const float*)d_in[7];
    const float *W3 = (const float*)d_in[8],  *b3 = (const float*)d_in[9];
    const float *fcW1 = (const float*)d_in[10], *fcb1 = (const float*)d_in[11];
    const float *fcW2 = (const float*)d_in[12], *fcb2 = (const float*)d_in[13];
    const float *g1 = (const float*)d_in[14], *be1 = (const float*)d_in[15];
    const float *g2 = (const float*)d_in[16], *be2 = (const float*)d_in[17];
    const float *g3 = (const float*)d_in[18], *be3 = (const float*)d_in[19];
    float* out = (float*)d_out;

    const int EB = (N_EDGES + 255) / 256;              // 3125
    const int NB1024 = (N_NODES + 1023) / 1024;        // 49
    const int AGG_B = (N_NODES * 16 + 255) / 256;      // 3125
    const int GEMM_B = (N_NODES + 63) / 64;            // 782

    k_count_xh<<<EB, 256>>>(ei, x);                    // our launch 0
    k_scan<<<NB1024, 1024>>>();                        // 1 (merged scan)
    k_fill<<<EB, 256>>>(ei, ew);                       // 2

    k_agg<<<AGG_B, 256>>>(-1, nullptr, nullptr);       // 3 (ncu capture slot)
    k_gemm<<<GEMM_B, 256>>>(W1, b1, 0, 1);
    k_agg<<<AGG_B, 256>>>(0, g1, be1);
    k_gemm<<<GEMM_B, 256>>>(W2, b2, 1, 1);
    k_agg<<<AGG_B, 256>>>(1, g2, be2);
    k_gemm<<<GEMM_B, 256>>>(W3, b3, 2, 0);

    k_norm_pool<<<64, 256>>>(g3, be3, batch);
    k_final<<<N_GRAPHS / 8, 256>>>(fcW1, fcb1, fcW2, fcb2, out);
}